// round 11
// baseline (speedup 1.0000x reference)
#include <cuda_runtime.h>
#include <cuda_bf16.h>

// Problem constants (fixed by the dataset)
#define Bn 4
#define Nn 50000
#define Dn 256
#define En 800000
#define NPTS (Bn * Nn)   // 200000
#define MAXDEG 96        // Poisson(32): P(deg>96) ~ 1e-18 over 50k nodes

// Predict: 1250 blocks x 8 warps = 10000 warps, 20 points each (exact)
#define PRED_BLOCKS 1250
#define PRED_WARPS  10000

// XPBD state, batch-interleaved: g_x[buf][4*n + b] = float4(x,y,z,pad).
__device__ float4 g_x[2][NPTS];

// Fixed-slot incidence table: node n owns g_slot[n*MAXDEG .. n*MAXDEG+deg).
// entry = {4*neighbor (pre-scaled float4 index), bitcast(L0)}; rows padded to
// a multiple of 4 with zero-contribution self-edges.
__device__ int  g_cnt[Nn];
__device__ int2 g_slot[Nn * MAXDEG];   // 38.4 MB

// ---------------------------------------------------------------------------
// Stage 1: x_pred = keypoints + tau * (hand_tokens @ head_w + head_b)
// Warp per point, GRID-STRIDE (20 points/warp): the weight-permute preamble
// runs 1250x instead of 25000x (it dominated R10's issue budget). Hot loop:
// 2 points per iteration SHARING one weight read -> per point: 1 LDG.128x2,
// 12 LDS (conflict-free stride-25 layout), 24 FMA, 15 shfl. Issue floor
// ~11us << DRAM floor 26us -> DRAM-bound.
// ---------------------------------------------------------------------------
__global__ __launch_bounds__(256) void predict_kernel(
    const float* __restrict__ kp, const float* __restrict__ ts,
    const float* __restrict__ ht, const float* __restrict__ hw,
    const float* __restrict__ hb)
{
    __shared__ float sw[25 * 32];   // lane l's 24 weights at sw[25l..25l+23]
    __shared__ float sb[3];
    int tid = threadIdx.x;
    for (int idx = tid; idx < Dn * 3; idx += 256) {
        int r = idx / 3, c = idx - 3 * r;
        int q    = (r & 127) >> 2;                       // owner lane
        int slot = ((r >> 7) ? 12 : 0) + 3 * (r & 3) + c;
        sw[25 * q + slot] = hw[idx];
    }
    if (tid < 3) sb[tid] = hb[tid];
    __syncthreads();

    int lane = tid & 31;
    int gw   = (blockIdx.x * 256 + tid) >> 5;   // 0..9999
    const float*  wl  = &sw[25 * lane];
    const float4* ht4 = reinterpret_cast<const float4*>(ht);

#pragma unroll 1
    for (int m = 0; m < 10; m++) {
        int p0 = gw + (2 * m + 0) * PRED_WARPS;
        int p1 = gw + (2 * m + 1) * PRED_WARPS;

        float4 u0 = __ldg(&ht4[(size_t)p0 * 64 + lane]);
        float4 u1 = __ldg(&ht4[(size_t)p0 * 64 + 32 + lane]);
        float4 v0 = __ldg(&ht4[(size_t)p1 * 64 + lane]);
        float4 v1 = __ldg(&ht4[(size_t)p1 * 64 + 32 + lane]);

        float hu[8] = {u0.x, u0.y, u0.z, u0.w, u1.x, u1.y, u1.z, u1.w};
        float hv[8] = {v0.x, v0.y, v0.z, v0.w, v1.x, v1.y, v1.z, v1.w};
        float a0 = 0.f, a1 = 0.f, a2 = 0.f;
        float b0 = 0.f, b1 = 0.f, b2 = 0.f;
#pragma unroll
        for (int i = 0; i < 8; i++) {
            float w0 = wl[3 * i + 0];   // shared by both points
            float w1 = wl[3 * i + 1];
            float w2 = wl[3 * i + 2];
            a0 = fmaf(hu[i], w0, a0); a1 = fmaf(hu[i], w1, a1); a2 = fmaf(hu[i], w2, a2);
            b0 = fmaf(hv[i], w0, b0); b1 = fmaf(hv[i], w1, b1); b2 = fmaf(hv[i], w2, b2);
        }
#pragma unroll
        for (int o = 16; o >= 1; o >>= 1) {
            a0 += __shfl_xor_sync(0xffffffffu, a0, o);
            a1 += __shfl_xor_sync(0xffffffffu, a1, o);
            a2 += __shfl_xor_sync(0xffffffffu, a2, o);
            b0 += __shfl_xor_sync(0xffffffffu, b0, o);
            b1 += __shfl_xor_sync(0xffffffffu, b1, o);
            b2 += __shfl_xor_sync(0xffffffffu, b2, o);
        }
        if (lane == 0) {
            int bi = p0 / Nn, ni = p0 - bi * Nn;
            float tau = fmaxf(1.0f - __ldg(&ts[bi]), 0.001f);
            g_x[0][4 * ni + bi] = make_float4(
                fmaf(tau, a0 + sb[0], __ldg(&kp[(size_t)p0 * 3 + 0])),
                fmaf(tau, a1 + sb[1], __ldg(&kp[(size_t)p0 * 3 + 1])),
                fmaf(tau, a2 + sb[2], __ldg(&kp[(size_t)p0 * 3 + 2])), 0.0f);
            int bj = p1 / Nn, nj = p1 - bj * Nn;
            float tau1 = fmaxf(1.0f - __ldg(&ts[bj]), 0.001f);
            g_x[0][4 * nj + bj] = make_float4(
                fmaf(tau1, b0 + sb[0], __ldg(&kp[(size_t)p1 * 3 + 0])),
                fmaf(tau1, b1 + sb[1], __ldg(&kp[(size_t)p1 * 3 + 1])),
                fmaf(tau1, b2 + sb[2], __ldg(&kp[(size_t)p1 * 3 + 2])), 0.0f);
        }
    }
}

// ---------------------------------------------------------------------------
// Incidence build (side stream, hidden under predict).
// ---------------------------------------------------------------------------
__global__ __launch_bounds__(256) void zero_kernel()
{
    int i = blockIdx.x * blockDim.x + threadIdx.x;
    if (i < Nn) g_cnt[i] = 0;
}

__global__ __launch_bounds__(256) void fill_kernel(
    const int* __restrict__ ei, const float* __restrict__ rest)
{
    int e = blockIdx.x * blockDim.x + threadIdx.x;
    if (e >= En) return;
    int s  = __ldg(&ei[e]);
    int d  = __ldg(&ei[En + e]);
    int L0 = __float_as_int(__ldg(&rest[e]));
    int cs = atomicAdd(&g_cnt[s], 1);
    if (cs < MAXDEG) g_slot[s * MAXDEG + cs] = make_int2(4 * d, L0);
    int cd = atomicAdd(&g_cnt[d], 1);
    if (cd < MAXDEG) g_slot[d * MAXDEG + cd] = make_int2(4 * s, L0);
}

__global__ __launch_bounds__(256) void pad_kernel()
{
    int n = blockIdx.x * blockDim.x + threadIdx.x;
    if (n >= Nn) return;
    int c = min(g_cnt[n], MAXDEG);
    int p = (c + 3) & ~3;                    // pad to multiple of 4
    int2 self = make_int2(4 * n, __float_as_int(1.0f));  // zero contribution
    for (int k = c; k < p; k++) g_slot[n * MAXDEG + k] = self;
    g_cnt[n] = p;
}

// ---------------------------------------------------------------------------
// One XPBD Jacobi iteration. FOUR threads per (node, batch) (t = 16n+4h+b):
// quarter h walks groups k = 4h, 4h+16, ...; batch-siblings' gathers form one
// contiguous 64B segment; quarters combined with shfl_xor(4)+shfl_xor(8).
// If `out` is non-null this is the LAST iteration: h==0 threads emit
// v_eff = (x_new - kp)/tau directly (final kernel fused away).
// Grid exact: 800000 = 6250 x 128.
// ---------------------------------------------------------------------------
__global__ __launch_bounds__(128) void node_kernel(
    int from, int to,
    const float* __restrict__ kp, const float* __restrict__ ts,
    float* __restrict__ out)
{
    int t = blockIdx.x * 128 + threadIdx.x;
    int n = t >> 4;
    int b = t & 3;
    int h = (t >> 2) & 3;

    const float4* __restrict__ xin = g_x[from];
    float4 own = __ldg(&xin[4 * n + b]);

    int deg = __ldg(&g_cnt[n]);              // multiple of 4
    const int2* row = &g_slot[n * MAXDEG];

    float ax = 0.f, ay = 0.f, az = 0.f;

#pragma unroll 2
    for (int k = 4 * h; k < deg; k += 16) {
        int4 ea = __ldg(reinterpret_cast<const int4*>(row + k));
        int4 eb = __ldg(reinterpret_cast<const int4*>(row + k + 2));
        int   js[4]  = {ea.x, ea.z, eb.x, eb.z};    // already 4*j
        float L0s[4] = {__int_as_float(ea.y), __int_as_float(ea.w),
                        __int_as_float(eb.y), __int_as_float(eb.w)};
        float4 xj[4];
#pragma unroll
        for (int i = 0; i < 4; i++)
            xj[i] = __ldg(&xin[js[i] + b]);
#pragma unroll
        for (int i = 0; i < 4; i++) {
            float dx = own.x - xj[i].x;
            float dy = own.y - xj[i].y;
            float dz = own.z - xj[i].z;
            float d2 = fmaf(dx, dx, fmaf(dy, dy, dz * dz));
            float r  = rsqrtf(fmaxf(d2, 1e-24f));
            float f  = fmaf(L0s[i], r, -1.0f);      // 2x true scale
            ax += fminf(fmaxf(f * dx, -0.3f), 0.3f);
            ay += fminf(fmaxf(f * dy, -0.3f), 0.3f);
            az += fminf(fmaxf(f * dz, -0.3f), 0.3f);
        }
    }

    // combine the four quarters (partners differ in bits 2..3 of t)
    ax += __shfl_xor_sync(0xffffffffu, ax, 4);
    ay += __shfl_xor_sync(0xffffffffu, ay, 4);
    az += __shfl_xor_sync(0xffffffffu, az, 4);
    ax += __shfl_xor_sync(0xffffffffu, ax, 8);
    ay += __shfl_xor_sync(0xffffffffu, ay, 8);
    az += __shfl_xor_sync(0xffffffffu, az, 8);

    if (h == 0) {
        float nx = fmaf(0.5f, ax, own.x);
        float ny = fmaf(0.5f, ay, own.y);
        float nz = fmaf(0.5f, az, own.z);
        if (out == nullptr) {
            g_x[to][4 * n + b] = make_float4(nx, ny, nz, 0.0f);
        } else {
            // fused final: v_eff = (x_new - kp) / tau
            float inv_tau = 1.0f / fmaxf(1.0f - __ldg(&ts[b]), 0.001f);
            size_t o = (size_t)(b * Nn + n) * 3;
            out[o + 0] = (nx - __ldg(&kp[o + 0])) * inv_tau;
            out[o + 1] = (ny - __ldg(&kp[o + 1])) * inv_tau;
            out[o + 2] = (nz - __ldg(&kp[o + 2])) * inv_tau;
        }
    }
}

extern "C" void kernel_launch(void* const* d_in, const int* in_sizes, int n_in,
                              void* d_out, int out_size)
{
    const float* kp   = (const float*)d_in[0];  // keypoints   (B,N,3)
    const float* ts   = (const float*)d_in[1];  // timesteps   (B,)
    const float* ht   = (const float*)d_in[2];  // hand_tokens (B,N,D)
    const float* hw   = (const float*)d_in[3];  // head_w      (D,3)
    const float* hb   = (const float*)d_in[4];  // head_b      (3,)
    const int*   ei   = (const int*)  d_in[5];  // edge_index  (2,E)
    const float* rest = (const float*)d_in[6];  // rest_lengths(E,)
    float*       out  = (float*)d_out;          // v_eff       (B,N,3)

    (void)in_sizes; (void)n_in; (void)out_size;

    // Side stream + fork/join events, created once on the first (uncaptured)
    // correctness call. Host-side objects only.
    static cudaStream_t side = nullptr;
    static cudaEvent_t  ev_fork = nullptr, ev_join = nullptr;
    if (side == nullptr) {
        cudaStreamCreateWithFlags(&side, cudaStreamNonBlocking);
        cudaEventCreateWithFlags(&ev_fork, cudaEventDisableTiming);
        cudaEventCreateWithFlags(&ev_join, cudaEventDisableTiming);
    }

    const int nb_nodes = (Nn + 255) / 256;
    const int nb_edges = (En + 255) / 256;
    const int nb_node4 = (4 * NPTS) / 128;     // 6250, exact

    // Fork: incidence build on side stream, concurrent with predict.
    cudaEventRecord(ev_fork, 0);
    cudaStreamWaitEvent(side, ev_fork, 0);
    zero_kernel<<<nb_nodes, 256, 0, side>>>();
    fill_kernel<<<nb_edges, 256, 0, side>>>(ei, rest);
    pad_kernel <<<nb_nodes, 256, 0, side>>>();

    // Stage 1 on the main stream, overlapping the build
    predict_kernel<<<PRED_BLOCKS, 256>>>(kp, ts, ht, hw, hb);

    // Join
    cudaEventRecord(ev_join, side);
    cudaStreamWaitEvent(0, ev_join, 0);

    // Stage 2: 4 Jacobi XPBD iterations; the 4th fuses the velocity output
    node_kernel<<<nb_node4, 128>>>(0, 1, kp, ts, nullptr);
    node_kernel<<<nb_node4, 128>>>(1, 0, kp, ts, nullptr);
    node_kernel<<<nb_node4, 128>>>(0, 1, kp, ts, nullptr);
    node_kernel<<<nb_node4, 128>>>(1, 0, kp, ts, out);
}

// round 12
// speedup vs baseline: 1.0968x; 1.0968x over previous
#include <cuda_runtime.h>
#include <cuda_bf16.h>

// Problem constants (fixed by the dataset)
#define Bn 4
#define Nn 50000
#define Dn 256
#define En 800000
#define NPTS (Bn * Nn)   // 200000
#define MAXDEG 96        // Poisson(32): P(deg>96) ~ 1e-18 over 50k nodes

// Predict: 1250 blocks x 8 warps = 10000 warps, 20 points each (exact)
#define PRED_BLOCKS 1250
#define PRED_WARPS  10000

// XPBD state, batch-interleaved: g_x[buf][4*n + b] = float4(x,y,z,pad).
__device__ float4 g_x[2][NPTS];

// Fixed-slot incidence table: node n owns g_slot[n*MAXDEG .. n*MAXDEG+deg).
// entry = {4*neighbor (pre-scaled float4 index), bitcast(L0)}; rows padded to
// a multiple of 4 with zero-contribution self-edges.
__device__ int  g_cnt[Nn];
__device__ int2 g_slot[Nn * MAXDEG];   // 38.4 MB

// ---------------------------------------------------------------------------
// Stage 1 (best variant, R11): warp per point, grid-stride 20 points/warp,
// 2 points per iteration sharing one conflict-free smem weight read.
// ---------------------------------------------------------------------------
__global__ __launch_bounds__(256) void predict_kernel(
    const float* __restrict__ kp, const float* __restrict__ ts,
    const float* __restrict__ ht, const float* __restrict__ hw,
    const float* __restrict__ hb)
{
    __shared__ float sw[25 * 32];   // lane l's 24 weights at sw[25l..25l+23]
    __shared__ float sb[3];
    int tid = threadIdx.x;
    for (int idx = tid; idx < Dn * 3; idx += 256) {
        int r = idx / 3, c = idx - 3 * r;
        int q    = (r & 127) >> 2;                       // owner lane
        int slot = ((r >> 7) ? 12 : 0) + 3 * (r & 3) + c;
        sw[25 * q + slot] = hw[idx];
    }
    if (tid < 3) sb[tid] = hb[tid];
    __syncthreads();

    int lane = tid & 31;
    int gw   = (blockIdx.x * 256 + tid) >> 5;   // 0..9999
    const float*  wl  = &sw[25 * lane];
    const float4* ht4 = reinterpret_cast<const float4*>(ht);

#pragma unroll 1
    for (int m = 0; m < 10; m++) {
        int p0 = gw + (2 * m + 0) * PRED_WARPS;
        int p1 = gw + (2 * m + 1) * PRED_WARPS;

        float4 u0 = __ldg(&ht4[(size_t)p0 * 64 + lane]);
        float4 u1 = __ldg(&ht4[(size_t)p0 * 64 + 32 + lane]);
        float4 v0 = __ldg(&ht4[(size_t)p1 * 64 + lane]);
        float4 v1 = __ldg(&ht4[(size_t)p1 * 64 + 32 + lane]);

        float hu[8] = {u0.x, u0.y, u0.z, u0.w, u1.x, u1.y, u1.z, u1.w};
        float hv[8] = {v0.x, v0.y, v0.z, v0.w, v1.x, v1.y, v1.z, v1.w};
        float a0 = 0.f, a1 = 0.f, a2 = 0.f;
        float b0 = 0.f, b1 = 0.f, b2 = 0.f;
#pragma unroll
        for (int i = 0; i < 8; i++) {
            float w0 = wl[3 * i + 0];   // shared by both points
            float w1 = wl[3 * i + 1];
            float w2 = wl[3 * i + 2];
            a0 = fmaf(hu[i], w0, a0); a1 = fmaf(hu[i], w1, a1); a2 = fmaf(hu[i], w2, a2);
            b0 = fmaf(hv[i], w0, b0); b1 = fmaf(hv[i], w1, b1); b2 = fmaf(hv[i], w2, b2);
        }
#pragma unroll
        for (int o = 16; o >= 1; o >>= 1) {
            a0 += __shfl_xor_sync(0xffffffffu, a0, o);
            a1 += __shfl_xor_sync(0xffffffffu, a1, o);
            a2 += __shfl_xor_sync(0xffffffffu, a2, o);
            b0 += __shfl_xor_sync(0xffffffffu, b0, o);
            b1 += __shfl_xor_sync(0xffffffffu, b1, o);
            b2 += __shfl_xor_sync(0xffffffffu, b2, o);
        }
        if (lane == 0) {
            int bi = p0 / Nn, ni = p0 - bi * Nn;
            float tau = fmaxf(1.0f - __ldg(&ts[bi]), 0.001f);
            g_x[0][4 * ni + bi] = make_float4(
                fmaf(tau, a0 + sb[0], __ldg(&kp[(size_t)p0 * 3 + 0])),
                fmaf(tau, a1 + sb[1], __ldg(&kp[(size_t)p0 * 3 + 1])),
                fmaf(tau, a2 + sb[2], __ldg(&kp[(size_t)p0 * 3 + 2])), 0.0f);
            int bj = p1 / Nn, nj = p1 - bj * Nn;
            float tau1 = fmaxf(1.0f - __ldg(&ts[bj]), 0.001f);
            g_x[0][4 * nj + bj] = make_float4(
                fmaf(tau1, b0 + sb[0], __ldg(&kp[(size_t)p1 * 3 + 0])),
                fmaf(tau1, b1 + sb[1], __ldg(&kp[(size_t)p1 * 3 + 1])),
                fmaf(tau1, b2 + sb[2], __ldg(&kp[(size_t)p1 * 3 + 2])), 0.0f);
        }
    }
}

// ---------------------------------------------------------------------------
// Incidence build (side stream, hidden under predict).
// ---------------------------------------------------------------------------
__global__ __launch_bounds__(256) void zero_kernel()
{
    int i = blockIdx.x * blockDim.x + threadIdx.x;
    if (i < Nn) g_cnt[i] = 0;
}

__global__ __launch_bounds__(256) void fill_kernel(
    const int* __restrict__ ei, const float* __restrict__ rest)
{
    int e = blockIdx.x * blockDim.x + threadIdx.x;
    if (e >= En) return;
    int s  = __ldg(&ei[e]);
    int d  = __ldg(&ei[En + e]);
    int L0 = __float_as_int(__ldg(&rest[e]));
    int cs = atomicAdd(&g_cnt[s], 1);
    if (cs < MAXDEG) g_slot[s * MAXDEG + cs] = make_int2(4 * d, L0);
    int cd = atomicAdd(&g_cnt[d], 1);
    if (cd < MAXDEG) g_slot[d * MAXDEG + cd] = make_int2(4 * s, L0);
}

__global__ __launch_bounds__(256) void pad_kernel()
{
    int n = blockIdx.x * blockDim.x + threadIdx.x;
    if (n >= Nn) return;
    int c = min(g_cnt[n], MAXDEG);
    int p = (c + 3) & ~3;                    // pad to multiple of 4
    int2 self = make_int2(4 * n, __float_as_int(1.0f));  // zero contribution
    for (int k = c; k < p; k++) g_slot[n * MAXDEG + k] = self;
    g_cnt[n] = p;
}

// ---------------------------------------------------------------------------
// One XPBD Jacobi iteration (best variant, R8): TWO threads per (node,batch),
// half h walks groups k = 4h, 4h+8, ... with next-group entry prefetch.
// Layout t = 8n + 4h + b: batch-siblings' gathers form one contiguous 64B
// segment. Halves combined with shfl_xor(4); h==0 writes.
// If `out` != null (last iteration) h==0 emits v_eff = (x_new - kp)/tau.
// Grid exact: 400000 = 3125 x 128.
// ---------------------------------------------------------------------------
__global__ __launch_bounds__(128) void node_kernel(
    int from, int to,
    const float* __restrict__ kp, const float* __restrict__ ts,
    float* __restrict__ out)
{
    int t = blockIdx.x * 128 + threadIdx.x;
    int n = t >> 3;
    int b = t & 3;
    int h = (t >> 2) & 1;

    const float4* __restrict__ xin = g_x[from];
    float4 own = __ldg(&xin[4 * n + b]);

    int deg = __ldg(&g_cnt[n]);              // multiple of 4
    const int2* row = &g_slot[n * MAXDEG];

    float ax = 0.f, ay = 0.f, az = 0.f;

    int k = 4 * h;
    if (k < deg) {
        int4 ea = __ldg(reinterpret_cast<const int4*>(row + k));
        int4 eb = __ldg(reinterpret_cast<const int4*>(row + k + 2));
        while (true) {
            int kn = k + 8;
            int4 na, nb;
            bool more = (kn < deg);
            if (more) {                      // prefetch next group's entries
                na = __ldg(reinterpret_cast<const int4*>(row + kn));
                nb = __ldg(reinterpret_cast<const int4*>(row + kn + 2));
            }
            int   js[4]  = {ea.x, ea.z, eb.x, eb.z};    // already 4*j
            float L0s[4] = {__int_as_float(ea.y), __int_as_float(ea.w),
                            __int_as_float(eb.y), __int_as_float(eb.w)};
            float4 xj[4];
#pragma unroll
            for (int i = 0; i < 4; i++)
                xj[i] = __ldg(&xin[js[i] + b]);
#pragma unroll
            for (int i = 0; i < 4; i++) {
                float dx = own.x - xj[i].x;
                float dy = own.y - xj[i].y;
                float dz = own.z - xj[i].z;
                float d2 = fmaf(dx, dx, fmaf(dy, dy, dz * dz));
                float r  = rsqrtf(fmaxf(d2, 1e-24f));
                float f  = fmaf(L0s[i], r, -1.0f);      // 2x true scale
                ax += fminf(fmaxf(f * dx, -0.3f), 0.3f);
                ay += fminf(fmaxf(f * dy, -0.3f), 0.3f);
                az += fminf(fmaxf(f * dz, -0.3f), 0.3f);
            }
            if (!more) break;
            ea = na; eb = nb; k = kn;
        }
    }

    // combine the two halves (partner differs only in h -> lane xor 4)
    ax += __shfl_xor_sync(0xffffffffu, ax, 4);
    ay += __shfl_xor_sync(0xffffffffu, ay, 4);
    az += __shfl_xor_sync(0xffffffffu, az, 4);

    if (h == 0) {
        float nx = fmaf(0.5f, ax, own.x);
        float ny = fmaf(0.5f, ay, own.y);
        float nz = fmaf(0.5f, az, own.z);
        if (out == nullptr) {
            g_x[to][4 * n + b] = make_float4(nx, ny, nz, 0.0f);
        } else {
            // fused final: v_eff = (x_new - kp) / tau
            float inv_tau = 1.0f / fmaxf(1.0f - __ldg(&ts[b]), 0.001f);
            size_t o = (size_t)(b * Nn + n) * 3;
            out[o + 0] = (nx - __ldg(&kp[o + 0])) * inv_tau;
            out[o + 1] = (ny - __ldg(&kp[o + 1])) * inv_tau;
            out[o + 2] = (nz - __ldg(&kp[o + 2])) * inv_tau;
        }
    }
}

extern "C" void kernel_launch(void* const* d_in, const int* in_sizes, int n_in,
                              void* d_out, int out_size)
{
    const float* kp   = (const float*)d_in[0];  // keypoints   (B,N,3)
    const float* ts   = (const float*)d_in[1];  // timesteps   (B,)
    const float* ht   = (const float*)d_in[2];  // hand_tokens (B,N,D)
    const float* hw   = (const float*)d_in[3];  // head_w      (D,3)
    const float* hb   = (const float*)d_in[4];  // head_b      (3,)
    const int*   ei   = (const int*)  d_in[5];  // edge_index  (2,E)
    const float* rest = (const float*)d_in[6];  // rest_lengths(E,)
    float*       out  = (float*)d_out;          // v_eff       (B,N,3)

    (void)in_sizes; (void)n_in; (void)out_size;

    // Side stream + fork/join events, created once on the first (uncaptured)
    // correctness call. Host-side objects only.
    static cudaStream_t side = nullptr;
    static cudaEvent_t  ev_fork = nullptr, ev_join = nullptr;
    if (side == nullptr) {
        cudaStreamCreateWithFlags(&side, cudaStreamNonBlocking);
        cudaEventCreateWithFlags(&ev_fork, cudaEventDisableTiming);
        cudaEventCreateWithFlags(&ev_join, cudaEventDisableTiming);
    }

    const int nb_nodes = (Nn + 255) / 256;
    const int nb_edges = (En + 255) / 256;
    const int nb_node2 = (2 * NPTS) / 128;     // 3125, exact

    // Fork: incidence build on side stream, concurrent with predict.
    cudaEventRecord(ev_fork, 0);
    cudaStreamWaitEvent(side, ev_fork, 0);
    zero_kernel<<<nb_nodes, 256, 0, side>>>();
    fill_kernel<<<nb_edges, 256, 0, side>>>(ei, rest);
    pad_kernel <<<nb_nodes, 256, 0, side>>>();

    // Stage 1 on the main stream, overlapping the build
    predict_kernel<<<PRED_BLOCKS, 256>>>(kp, ts, ht, hw, hb);

    // Join
    cudaEventRecord(ev_join, side);
    cudaStreamWaitEvent(0, ev_join, 0);

    // Stage 2: 4 Jacobi XPBD iterations; the 4th fuses the velocity output
    node_kernel<<<nb_node2, 128>>>(0, 1, kp, ts, nullptr);
    node_kernel<<<nb_node2, 128>>>(1, 0, kp, ts, nullptr);
    node_kernel<<<nb_node2, 128>>>(0, 1, kp, ts, nullptr);
    node_kernel<<<nb_node2, 128>>>(1, 0, kp, ts, out);
}

// round 13
// speedup vs baseline: 1.1610x; 1.0586x over previous
#include <cuda_runtime.h>
#include <cuda_bf16.h>

// Problem constants (fixed by the dataset)
#define Bn 4
#define Nn 50000
#define Dn 256
#define En 800000
#define NPTS (Bn * Nn)   // 200000
#define MAXDEG 96        // Poisson(32): P(deg>96) ~ 1e-18 over 50k nodes

// Predict: 1250 blocks x 8 warps = 10000 warps, 20 points each (exact)
#define PRED_BLOCKS 1250
#define PRED_WARPS  10000

// XPBD state, batch-interleaved: g_x[buf][4*n + b] = float4(x,y,z,pad).
__device__ float4 g_x[2][NPTS];

// Fixed-slot incidence table: node n owns g_slot[n*MAXDEG .. n*MAXDEG+deg).
// entry = {4*neighbor (pre-scaled float4 index), bitcast(L0)}; rows padded to
// a multiple of 4 with zero-contribution self-edges.
__device__ int  g_cnt[Nn];
__device__ int2 g_slot[Nn * MAXDEG];   // 38.4 MB

// ---------------------------------------------------------------------------
// Stage 1: x_pred = keypoints + tau * (hand_tokens @ head_w + head_b)
// Warp per point, grid-stride 20 points/warp, 2 points per iteration sharing
// one conflict-free smem weight read. SOFTWARE-PIPELINED: iteration m+1's
// 4 LDG.128 are issued BEFORE iteration m's FMA/shfl/store body, so loads
// stay in flight across the compute tail instead of stalling cold at the
// top of each iteration (R12 ncu: DRAM 59.5%, issue 48% = latency-exposed).
// ---------------------------------------------------------------------------
__global__ __launch_bounds__(256) void predict_kernel(
    const float* __restrict__ kp, const float* __restrict__ ts,
    const float* __restrict__ ht, const float* __restrict__ hw,
    const float* __restrict__ hb)
{
    __shared__ float sw[25 * 32];   // lane l's 24 weights at sw[25l..25l+23]
    __shared__ float sb[3];
    int tid = threadIdx.x;
    for (int idx = tid; idx < Dn * 3; idx += 256) {
        int r = idx / 3, c = idx - 3 * r;
        int q    = (r & 127) >> 2;                       // owner lane
        int slot = ((r >> 7) ? 12 : 0) + 3 * (r & 3) + c;
        sw[25 * q + slot] = hw[idx];
    }
    if (tid < 3) sb[tid] = hb[tid];
    __syncthreads();

    int lane = tid & 31;
    int gw   = (blockIdx.x * 256 + tid) >> 5;   // 0..9999
    const float*  wl  = &sw[25 * lane];
    const float4* ht4 = reinterpret_cast<const float4*>(ht);

    // prologue: loads for m = 0
    int p0 = gw;
    int p1 = gw + PRED_WARPS;
    float4 u0 = __ldg(&ht4[(size_t)p0 * 64 + lane]);
    float4 u1 = __ldg(&ht4[(size_t)p0 * 64 + 32 + lane]);
    float4 v0 = __ldg(&ht4[(size_t)p1 * 64 + lane]);
    float4 v1 = __ldg(&ht4[(size_t)p1 * 64 + 32 + lane]);

#pragma unroll 1
    for (int m = 0; m < 10; m++) {
        // prefetch m+1 (in flight across this iteration's compute + store)
        float4 nu0 = u0, nu1 = u1, nv0 = v0, nv1 = v1;
        if (m < 9) {
            int q0 = p0 + 2 * PRED_WARPS;
            int q1 = p1 + 2 * PRED_WARPS;
            nu0 = __ldg(&ht4[(size_t)q0 * 64 + lane]);
            nu1 = __ldg(&ht4[(size_t)q0 * 64 + 32 + lane]);
            nv0 = __ldg(&ht4[(size_t)q1 * 64 + lane]);
            nv1 = __ldg(&ht4[(size_t)q1 * 64 + 32 + lane]);
        }

        float hu[8] = {u0.x, u0.y, u0.z, u0.w, u1.x, u1.y, u1.z, u1.w};
        float hv[8] = {v0.x, v0.y, v0.z, v0.w, v1.x, v1.y, v1.z, v1.w};
        float a0 = 0.f, a1 = 0.f, a2 = 0.f;
        float b0 = 0.f, b1 = 0.f, b2 = 0.f;
#pragma unroll
        for (int i = 0; i < 8; i++) {
            float w0 = wl[3 * i + 0];   // shared by both points
            float w1 = wl[3 * i + 1];
            float w2 = wl[3 * i + 2];
            a0 = fmaf(hu[i], w0, a0); a1 = fmaf(hu[i], w1, a1); a2 = fmaf(hu[i], w2, a2);
            b0 = fmaf(hv[i], w0, b0); b1 = fmaf(hv[i], w1, b1); b2 = fmaf(hv[i], w2, b2);
        }
#pragma unroll
        for (int o = 16; o >= 1; o >>= 1) {
            a0 += __shfl_xor_sync(0xffffffffu, a0, o);
            a1 += __shfl_xor_sync(0xffffffffu, a1, o);
            a2 += __shfl_xor_sync(0xffffffffu, a2, o);
            b0 += __shfl_xor_sync(0xffffffffu, b0, o);
            b1 += __shfl_xor_sync(0xffffffffu, b1, o);
            b2 += __shfl_xor_sync(0xffffffffu, b2, o);
        }
        if (lane == 0) {
            int bi = p0 / Nn, ni = p0 - bi * Nn;
            float tau = fmaxf(1.0f - __ldg(&ts[bi]), 0.001f);
            g_x[0][4 * ni + bi] = make_float4(
                fmaf(tau, a0 + sb[0], __ldg(&kp[(size_t)p0 * 3 + 0])),
                fmaf(tau, a1 + sb[1], __ldg(&kp[(size_t)p0 * 3 + 1])),
                fmaf(tau, a2 + sb[2], __ldg(&kp[(size_t)p0 * 3 + 2])), 0.0f);
            int bj = p1 / Nn, nj = p1 - bj * Nn;
            float tau1 = fmaxf(1.0f - __ldg(&ts[bj]), 0.001f);
            g_x[0][4 * nj + bj] = make_float4(
                fmaf(tau1, b0 + sb[0], __ldg(&kp[(size_t)p1 * 3 + 0])),
                fmaf(tau1, b1 + sb[1], __ldg(&kp[(size_t)p1 * 3 + 1])),
                fmaf(tau1, b2 + sb[2], __ldg(&kp[(size_t)p1 * 3 + 2])), 0.0f);
        }

        u0 = nu0; u1 = nu1; v0 = nv0; v1 = nv1;
        p0 += 2 * PRED_WARPS; p1 += 2 * PRED_WARPS;
    }
}

// ---------------------------------------------------------------------------
// Incidence build (side stream, hidden under predict).
// ---------------------------------------------------------------------------
__global__ __launch_bounds__(256) void zero_kernel()
{
    int i = blockIdx.x * blockDim.x + threadIdx.x;
    if (i < Nn) g_cnt[i] = 0;
}

__global__ __launch_bounds__(256) void fill_kernel(
    const int* __restrict__ ei, const float* __restrict__ rest)
{
    int e = blockIdx.x * blockDim.x + threadIdx.x;
    if (e >= En) return;
    int s  = __ldg(&ei[e]);
    int d  = __ldg(&ei[En + e]);
    int L0 = __float_as_int(__ldg(&rest[e]));
    int cs = atomicAdd(&g_cnt[s], 1);
    if (cs < MAXDEG) g_slot[s * MAXDEG + cs] = make_int2(4 * d, L0);
    int cd = atomicAdd(&g_cnt[d], 1);
    if (cd < MAXDEG) g_slot[d * MAXDEG + cd] = make_int2(4 * s, L0);
}

__global__ __launch_bounds__(256) void pad_kernel()
{
    int n = blockIdx.x * blockDim.x + threadIdx.x;
    if (n >= Nn) return;
    int c = min(g_cnt[n], MAXDEG);
    int p = (c + 3) & ~3;                    // pad to multiple of 4
    int2 self = make_int2(4 * n, __float_as_int(1.0f));  // zero contribution
    for (int k = c; k < p; k++) g_slot[n * MAXDEG + k] = self;
    g_cnt[n] = p;
}

// ---------------------------------------------------------------------------
// One XPBD Jacobi iteration (R8 config — measured best): TWO threads per
// (node,batch), half h walks groups k = 4h, 4h+8, ... with next-group entry
// prefetch. Layout t = 8n + 4h + b. Halves combined with shfl_xor(4).
// If `out` != null (last iteration) h==0 emits v_eff = (x_new - kp)/tau.
// Grid exact: 400000 = 3125 x 128.
// ---------------------------------------------------------------------------
__global__ __launch_bounds__(128) void node_kernel(
    int from, int to,
    const float* __restrict__ kp, const float* __restrict__ ts,
    float* __restrict__ out)
{
    int t = blockIdx.x * 128 + threadIdx.x;
    int n = t >> 3;
    int b = t & 3;
    int h = (t >> 2) & 1;

    const float4* __restrict__ xin = g_x[from];
    float4 own = __ldg(&xin[4 * n + b]);

    int deg = __ldg(&g_cnt[n]);              // multiple of 4
    const int2* row = &g_slot[n * MAXDEG];

    float ax = 0.f, ay = 0.f, az = 0.f;

    int k = 4 * h;
    if (k < deg) {
        int4 ea = __ldg(reinterpret_cast<const int4*>(row + k));
        int4 eb = __ldg(reinterpret_cast<const int4*>(row + k + 2));
        while (true) {
            int kn = k + 8;
            int4 na, nb;
            bool more = (kn < deg);
            if (more) {                      // prefetch next group's entries
                na = __ldg(reinterpret_cast<const int4*>(row + kn));
                nb = __ldg(reinterpret_cast<const int4*>(row + kn + 2));
            }
            int   js[4]  = {ea.x, ea.z, eb.x, eb.z};    // already 4*j
            float L0s[4] = {__int_as_float(ea.y), __int_as_float(ea.w),
                            __int_as_float(eb.y), __int_as_float(eb.w)};
            float4 xj[4];
#pragma unroll
            for (int i = 0; i < 4; i++)
                xj[i] = __ldg(&xin[js[i] + b]);
#pragma unroll
            for (int i = 0; i < 4; i++) {
                float dx = own.x - xj[i].x;
                float dy = own.y - xj[i].y;
                float dz = own.z - xj[i].z;
                float d2 = fmaf(dx, dx, fmaf(dy, dy, dz * dz));
                float r  = rsqrtf(fmaxf(d2, 1e-24f));
                float f  = fmaf(L0s[i], r, -1.0f);      // 2x true scale
                ax += fminf(fmaxf(f * dx, -0.3f), 0.3f);
                ay += fminf(fmaxf(f * dy, -0.3f), 0.3f);
                az += fminf(fmaxf(f * dz, -0.3f), 0.3f);
            }
            if (!more) break;
            ea = na; eb = nb; k = kn;
        }
    }

    // combine the two halves (partner differs only in h -> lane xor 4)
    ax += __shfl_xor_sync(0xffffffffu, ax, 4);
    ay += __shfl_xor_sync(0xffffffffu, ay, 4);
    az += __shfl_xor_sync(0xffffffffu, az, 4);

    if (h == 0) {
        float nx = fmaf(0.5f, ax, own.x);
        float ny = fmaf(0.5f, ay, own.y);
        float nz = fmaf(0.5f, az, own.z);
        if (out == nullptr) {
            g_x[to][4 * n + b] = make_float4(nx, ny, nz, 0.0f);
        } else {
            // fused final: v_eff = (x_new - kp) / tau
            float inv_tau = 1.0f / fmaxf(1.0f - __ldg(&ts[b]), 0.001f);
            size_t o = (size_t)(b * Nn + n) * 3;
            out[o + 0] = (nx - __ldg(&kp[o + 0])) * inv_tau;
            out[o + 1] = (ny - __ldg(&kp[o + 1])) * inv_tau;
            out[o + 2] = (nz - __ldg(&kp[o + 2])) * inv_tau;
        }
    }
}

extern "C" void kernel_launch(void* const* d_in, const int* in_sizes, int n_in,
                              void* d_out, int out_size)
{
    const float* kp   = (const float*)d_in[0];  // keypoints   (B,N,3)
    const float* ts   = (const float*)d_in[1];  // timesteps   (B,)
    const float* ht   = (const float*)d_in[2];  // hand_tokens (B,N,D)
    const float* hw   = (const float*)d_in[3];  // head_w      (D,3)
    const float* hb   = (const float*)d_in[4];  // head_b      (3,)
    const int*   ei   = (const int*)  d_in[5];  // edge_index  (2,E)
    const float* rest = (const float*)d_in[6];  // rest_lengths(E,)
    float*       out  = (float*)d_out;          // v_eff       (B,N,3)

    (void)in_sizes; (void)n_in; (void)out_size;

    // Side stream + fork/join events, created once on the first (uncaptured)
    // correctness call. Host-side objects only.
    static cudaStream_t side = nullptr;
    static cudaEvent_t  ev_fork = nullptr, ev_join = nullptr;
    if (side == nullptr) {
        cudaStreamCreateWithFlags(&side, cudaStreamNonBlocking);
        cudaEventCreateWithFlags(&ev_fork, cudaEventDisableTiming);
        cudaEventCreateWithFlags(&ev_join, cudaEventDisableTiming);
    }

    const int nb_nodes = (Nn + 255) / 256;
    const int nb_edges = (En + 255) / 256;
    const int nb_node2 = (2 * NPTS) / 128;     // 3125, exact

    // Fork: incidence build on side stream, concurrent with predict.
    cudaEventRecord(ev_fork, 0);
    cudaStreamWaitEvent(side, ev_fork, 0);
    zero_kernel<<<nb_nodes, 256, 0, side>>>();
    fill_kernel<<<nb_edges, 256, 0, side>>>(ei, rest);
    pad_kernel <<<nb_nodes, 256, 0, side>>>();

    // Stage 1 on the main stream, overlapping the build
    predict_kernel<<<PRED_BLOCKS, 256>>>(kp, ts, ht, hw, hb);

    // Join
    cudaEventRecord(ev_join, side);
    cudaStreamWaitEvent(0, ev_join, 0);

    // Stage 2: 4 Jacobi XPBD iterations; the 4th fuses the velocity output
    node_kernel<<<nb_node2, 128>>>(0, 1, kp, ts, nullptr);
    node_kernel<<<nb_node2, 128>>>(1, 0, kp, ts, nullptr);
    node_kernel<<<nb_node2, 128>>>(0, 1, kp, ts, nullptr);
    node_kernel<<<nb_node2, 128>>>(1, 0, kp, ts, out);
}